// round 1
// baseline (speedup 1.0000x reference)
#include <cuda_runtime.h>

// Problem constants
#define Bb 2
#define Ls 2048
#define Dm 1024
#define Hh 16
#define Dk 64
#define Dv 64
#define BHN (Bb*Hh)

// Scratch (static device arrays — no runtime allocation)
__device__ float g_Q[(size_t)Bb*Hh*Ls*Dk];   // 16 MB
__device__ float g_K[(size_t)Bb*Hh*Ls*Dk];   // 16 MB
__device__ float g_V[(size_t)Bb*Hh*Ls*Dv];   // 16 MB
__device__ float g_Z[(size_t)Bb*Ls*Hh*Dv];   // 16 MB, layout (B, L, H*Dv) = concat heads

// ---------------------------------------------------------------------------
// Kernel 1: QKV projections.  For each (sel in {q,k,v}, b, h):
//   Out[l][n] = sum_d X[b][l][d] * W[h][d][n] + bias[h][n]
// Tiled SGEMM: BM=128, BN=64, BK=32, 256 threads, each thread 8x4 outputs.
// ---------------------------------------------------------------------------
__global__ __launch_bounds__(256) void qkv_kernel(
    const float* __restrict__ X,
    const float* __restrict__ Wq, const float* __restrict__ bq,
    const float* __restrict__ Wk, const float* __restrict__ bk,
    const float* __restrict__ Wv, const float* __restrict__ bv)
{
    const int BM = 128, BN = 64, BK = 32;
    __shared__ float sa[BK][BM + 4];   // A tile, transposed (k-major)
    __shared__ float sb[BK][BN];       // W tile, direct

    int z   = blockIdx.y;              // 0..95
    int sel = z / BHN;
    int bh  = z - sel * BHN;
    int b   = bh / Hh;
    int h   = bh - b * Hh;

    const float* W; const float* bias; float* out;
    if (sel == 0)      { W = Wq; bias = bq; out = g_Q; }
    else if (sel == 1) { W = Wk; bias = bk; out = g_K; }
    else               { W = Wv; bias = bv; out = g_V; }
    W    += (size_t)h * Dm * Dk;
    bias += h * Dk;
    out  += (size_t)bh * Ls * Dk + (size_t)blockIdx.x * BM * Dk;
    const float* A = X + (size_t)b * Ls * Dm + (size_t)blockIdx.x * BM * Dm;

    int tid = threadIdx.x;
    int tx = tid & 15, ty = tid >> 4;

    float4 ra[4]; float4 rb[2];
    // Prologue loads (kt = 0)
#pragma unroll
    for (int i = 0; i < 4; i++) {
        int id = tid + 256 * i; int r = id >> 3, c4 = id & 7;
        ra[i] = *(const float4*)(A + (size_t)r * Dm + c4 * 4);
    }
#pragma unroll
    for (int i = 0; i < 2; i++) {
        int id = tid + 256 * i; int r = id >> 4, c4 = id & 15;
        rb[i] = *(const float4*)(W + (size_t)r * Dk + c4 * 4);
    }

    float acc[8][4] = {};
    const int NT = Dm / BK;
    for (int kt = 0; kt < NT; ++kt) {
        // commit staged tile to smem
#pragma unroll
        for (int i = 0; i < 4; i++) {
            int id = tid + 256 * i; int r = id >> 3, c4 = id & 7;
            sa[c4 * 4 + 0][r] = ra[i].x;
            sa[c4 * 4 + 1][r] = ra[i].y;
            sa[c4 * 4 + 2][r] = ra[i].z;
            sa[c4 * 4 + 3][r] = ra[i].w;
        }
#pragma unroll
        for (int i = 0; i < 2; i++) {
            int id = tid + 256 * i; int r = id >> 4, c4 = id & 15;
            *(float4*)&sb[r][c4 * 4] = rb[i];
        }
        __syncthreads();
        // prefetch next tile into registers (overlaps with compute)
        if (kt + 1 < NT) {
#pragma unroll
            for (int i = 0; i < 4; i++) {
                int id = tid + 256 * i; int r = id >> 3, c4 = id & 7;
                ra[i] = *(const float4*)(A + (size_t)r * Dm + (kt + 1) * BK + c4 * 4);
            }
#pragma unroll
            for (int i = 0; i < 2; i++) {
                int id = tid + 256 * i; int r = id >> 4, c4 = id & 15;
                rb[i] = *(const float4*)(W + (size_t)((kt + 1) * BK + r) * Dk + c4 * 4);
            }
        }
#pragma unroll
        for (int k = 0; k < BK; k++) {
            float4 a0 = *(float4*)&sa[k][ty * 8];
            float4 a1 = *(float4*)&sa[k][ty * 8 + 4];
            float4 b0 = *(float4*)&sb[k][tx * 4];
            float av[8] = {a0.x, a0.y, a0.z, a0.w, a1.x, a1.y, a1.z, a1.w};
            float bvv[4] = {b0.x, b0.y, b0.z, b0.w};
#pragma unroll
            for (int i = 0; i < 8; i++)
#pragma unroll
                for (int j = 0; j < 4; j++)
                    acc[i][j] += av[i] * bvv[j];
        }
        __syncthreads();
    }

    float4 bias4 = *(const float4*)(bias + tx * 4);
#pragma unroll
    for (int i = 0; i < 8; i++) {
        float4 v;
        v.x = acc[i][0] + bias4.x;
        v.y = acc[i][1] + bias4.y;
        v.z = acc[i][2] + bias4.z;
        v.w = acc[i][3] + bias4.w;
        *(float4*)(out + (size_t)(ty * 8 + i) * Dk + tx * 4) = v;
    }
}

// ---------------------------------------------------------------------------
// Kernel 2: flash attention per (b,h). One CTA = 128 query rows; streams KV
// in tiles of 128. S (128x128) staged in smem; online softmax; O in registers.
// Writes Z directly head-concatenated: g_Z[b][l][h*Dv + c].
// ---------------------------------------------------------------------------
#define QP 132   // padded pitch for transposed Q/K tiles

__global__ __launch_bounds__(256) void flash_kernel()
{
    extern __shared__ float sm[];
    float* qs  = sm;                   // [64][QP]  Q^T (scaled)
    float* ks  = qs + 64 * QP;         // [64][QP]  K^T
    float* vs  = ks + 64 * QP;         // [128][64] V
    float* ps  = vs + 128 * 64;        // [128][128] S / P
    float* rsc = ps + 128 * 128;       // [128] per-row rescale / inv-sum

    int bh = blockIdx.y;
    int q0 = blockIdx.x * 128;
    const float* Qg = g_Q + (size_t)bh * Ls * Dk + (size_t)q0 * Dk;
    const float* Kg = g_K + (size_t)bh * Ls * Dk;
    const float* Vg = g_V + (size_t)bh * Ls * Dv;
    int b = bh / Hh, h = bh - b * Hh;

    int tid = threadIdx.x;
    int tx = tid & 15, ty = tid >> 4;

    const float scale = 0.125f;        // 1/sqrt(64), folded into Q
#pragma unroll
    for (int i = 0; i < 8; i++) {
        int id = tid + 256 * i; int r = id >> 4, d4 = id & 15;
        float4 v = *(const float4*)(Qg + (size_t)r * Dk + d4 * 4);
        qs[(d4 * 4 + 0) * QP + r] = v.x * scale;
        qs[(d4 * 4 + 1) * QP + r] = v.y * scale;
        qs[(d4 * 4 + 2) * QP + r] = v.z * scale;
        qs[(d4 * 4 + 3) * QP + r] = v.w * scale;
    }

    float o[8][4] = {};
    float mi = -1e30f, li = 0.f;
    int rr = tid >> 1, half = tid & 1;

    for (int t = 0; t < Ls / 128; ++t) {
        // load K tile (transposed) and V tile (direct)
#pragma unroll
        for (int i = 0; i < 8; i++) {
            int id = tid + 256 * i; int r = id >> 4, d4 = id & 15;
            float4 v = *(const float4*)(Kg + (size_t)(t * 128 + r) * Dk + d4 * 4);
            ks[(d4 * 4 + 0) * QP + r] = v.x;
            ks[(d4 * 4 + 1) * QP + r] = v.y;
            ks[(d4 * 4 + 2) * QP + r] = v.z;
            ks[(d4 * 4 + 3) * QP + r] = v.w;
            float4 w = *(const float4*)(Vg + (size_t)(t * 128 + r) * Dv + d4 * 4);
            *(float4*)&vs[r * 64 + d4 * 4] = w;
        }
        __syncthreads();

        // Phase A: S = (Q*scale) K^T  (each thread an 8x8 tile of S)
        {
            float sacc[8][8] = {};
#pragma unroll 8
            for (int d = 0; d < 64; ++d) {
                float4 a0 = *(float4*)&qs[d * QP + ty * 8];
                float4 a1 = *(float4*)&qs[d * QP + ty * 8 + 4];
                float4 b0 = *(float4*)&ks[d * QP + tx * 8];
                float4 b1 = *(float4*)&ks[d * QP + tx * 8 + 4];
                float av[8] = {a0.x, a0.y, a0.z, a0.w, a1.x, a1.y, a1.z, a1.w};
                float bw[8] = {b0.x, b0.y, b0.z, b0.w, b1.x, b1.y, b1.z, b1.w};
#pragma unroll
                for (int i = 0; i < 8; i++)
#pragma unroll
                    for (int j = 0; j < 8; j++)
                        sacc[i][j] += av[i] * bw[j];
            }
#pragma unroll
            for (int i = 0; i < 8; i++) {
                *(float4*)&ps[(ty * 8 + i) * 128 + tx * 8] =
                    make_float4(sacc[i][0], sacc[i][1], sacc[i][2], sacc[i][3]);
                *(float4*)&ps[(ty * 8 + i) * 128 + tx * 8 + 4] =
                    make_float4(sacc[i][4], sacc[i][5], sacc[i][6], sacc[i][7]);
            }
        }
        __syncthreads();

        // Phase B: online softmax. Two threads per row (lanes t, t^1).
        {
            float* row = ps + rr * 128 + half * 64;
            float mx = -1e30f;
#pragma unroll 8
            for (int i = 0; i < 64; i++) mx = fmaxf(mx, row[i]);
            mx = fmaxf(mx, __shfl_xor_sync(0xffffffffu, mx, 1));
            float mnew  = fmaxf(mi, mx);
            float alpha = __expf(mi - mnew);
            float s = 0.f;
#pragma unroll 8
            for (int i = 0; i < 64; i++) {
                float p = __expf(row[i] - mnew);
                row[i] = p;
                s += p;
            }
            s += __shfl_xor_sync(0xffffffffu, s, 1);
            li = li * alpha + s;
            mi = mnew;
            if (half == 0) rsc[rr] = alpha;
        }
        __syncthreads();

        // Phase C: O = O*alpha + P V  (each thread 8 rows x 4 cols)
#pragma unroll
        for (int i = 0; i < 8; i++) {
            float al = rsc[ty * 8 + i];
#pragma unroll
            for (int j = 0; j < 4; j++) o[i][j] *= al;
        }
#pragma unroll 4
        for (int j = 0; j < 128; j++) {
            float4 bvv = *(float4*)&vs[j * 64 + tx * 4];
#pragma unroll
            for (int i = 0; i < 8; i++) {
                float a = ps[(ty * 8 + i) * 128 + j];   // broadcast read
                o[i][0] += a * bvv.x;
                o[i][1] += a * bvv.y;
                o[i][2] += a * bvv.z;
                o[i][3] += a * bvv.w;
            }
        }
        __syncthreads();
    }

    rsc[rr] = 1.0f / li;   // both pair threads write identical value
    __syncthreads();

    float* Zg = g_Z + ((size_t)(b * Ls + q0)) * (Hh * Dv) + h * Dv;
#pragma unroll
    for (int i = 0; i < 8; i++) {
        float inv = rsc[ty * 8 + i];
        float4 v = make_float4(o[i][0] * inv, o[i][1] * inv, o[i][2] * inv, o[i][3] * inv);
        *(float4*)(Zg + (size_t)(ty * 8 + i) * (Hh * Dv) + tx * 4) = v;
    }
}

// ---------------------------------------------------------------------------
// Kernel 3: output projection. out[m][n] = sum_e Z[m][e]*Wo[n][e] + bo[n]
// M=4096, N=1024, K=1024. Same SGEMM tiling; Wo tile transposed into smem.
// ---------------------------------------------------------------------------
__global__ __launch_bounds__(256) void oproj_kernel(
    const float* __restrict__ Wo, const float* __restrict__ bo,
    float* __restrict__ out)
{
    const int BM = 128, BN = 64, BK = 32;
    __shared__ float sa[BK][BM + 4];
    __shared__ float sb[BK][BN + 4];
    const int N = Dm;           // 1024
    const int K = Hh * Dv;      // 1024

    const float* A = g_Z + (size_t)blockIdx.x * BM * K;
    int n0 = blockIdx.y * BN;

    int tid = threadIdx.x;
    int tx = tid & 15, ty = tid >> 4;

    float4 ra[4]; float4 rb[2];
#pragma unroll
    for (int i = 0; i < 4; i++) {
        int id = tid + 256 * i; int r = id >> 3, c4 = id & 7;
        ra[i] = *(const float4*)(A + (size_t)r * K + c4 * 4);
    }
#pragma unroll
    for (int i = 0; i < 2; i++) {
        int id = tid + 256 * i; int r = id >> 3, c4 = id & 7;
        rb[i] = *(const float4*)(Wo + (size_t)(n0 + r) * K + c4 * 4);
    }

    float acc[8][4] = {};
    const int NT = K / BK;
    for (int kt = 0; kt < NT; ++kt) {
#pragma unroll
        for (int i = 0; i < 4; i++) {
            int id = tid + 256 * i; int r = id >> 3, c4 = id & 7;
            sa[c4 * 4 + 0][r] = ra[i].x;
            sa[c4 * 4 + 1][r] = ra[i].y;
            sa[c4 * 4 + 2][r] = ra[i].z;
            sa[c4 * 4 + 3][r] = ra[i].w;
        }
#pragma unroll
        for (int i = 0; i < 2; i++) {
            int id = tid + 256 * i; int r = id >> 3, c4 = id & 7;
            sb[c4 * 4 + 0][r] = rb[i].x;
            sb[c4 * 4 + 1][r] = rb[i].y;
            sb[c4 * 4 + 2][r] = rb[i].z;
            sb[c4 * 4 + 3][r] = rb[i].w;
        }
        __syncthreads();
        if (kt + 1 < NT) {
#pragma unroll
            for (int i = 0; i < 4; i++) {
                int id = tid + 256 * i; int r = id >> 3, c4 = id & 7;
                ra[i] = *(const float4*)(A + (size_t)r * K + (kt + 1) * BK + c4 * 4);
            }
#pragma unroll
            for (int i = 0; i < 2; i++) {
                int id = tid + 256 * i; int r = id >> 3, c4 = id & 7;
                rb[i] = *(const float4*)(Wo + (size_t)(n0 + r) * K + (kt + 1) * BK + c4 * 4);
            }
        }
#pragma unroll
        for (int k = 0; k < BK; k++) {
            float4 a0 = *(float4*)&sa[k][ty * 8];
            float4 a1 = *(float4*)&sa[k][ty * 8 + 4];
            float4 b0 = *(float4*)&sb[k][tx * 4];
            float av[8] = {a0.x, a0.y, a0.z, a0.w, a1.x, a1.y, a1.z, a1.w};
            float bw[4] = {b0.x, b0.y, b0.z, b0.w};
#pragma unroll
            for (int i = 0; i < 8; i++)
#pragma unroll
                for (int j = 0; j < 4; j++)
                    acc[i][j] += av[i] * bw[j];
        }
        __syncthreads();
    }

    float4 bias4 = *(const float4*)(bo + n0 + tx * 4);
#pragma unroll
    for (int i = 0; i < 8; i++) {
        float4 v;
        v.x = acc[i][0] + bias4.x;
        v.y = acc[i][1] + bias4.y;
        v.z = acc[i][2] + bias4.z;
        v.w = acc[i][3] + bias4.w;
        *(float4*)(out + (size_t)(blockIdx.x * BM + ty * 8 + i) * N + n0 + tx * 4) = v;
    }
}

// ---------------------------------------------------------------------------
extern "C" void kernel_launch(void* const* d_in, const int* in_sizes, int n_in,
                              void* d_out, int out_size)
{
    const float* X  = (const float*)d_in[0];
    const float* Wq = (const float*)d_in[1];
    const float* bq = (const float*)d_in[2];
    const float* Wk = (const float*)d_in[3];
    const float* bk = (const float*)d_in[4];
    const float* Wv = (const float*)d_in[5];
    const float* bv = (const float*)d_in[6];
    const float* Wo = (const float*)d_in[7];
    const float* bo = (const float*)d_in[8];
    float* out = (float*)d_out;

    (void)in_sizes; (void)n_in; (void)out_size;

    const int flash_smem = (64 * QP + 64 * QP + 128 * 64 + 128 * 128 + 128) * (int)sizeof(float);
    cudaFuncSetAttribute(flash_kernel, cudaFuncAttributeMaxDynamicSharedMemorySize, flash_smem);

    qkv_kernel<<<dim3(Ls / 128, 3 * BHN), 256>>>(X, Wq, bq, Wk, bk, Wv, bv);
    flash_kernel<<<dim3(Ls / 128, BHN), 256, flash_smem>>>();
    oproj_kernel<<<dim3((Bb * Ls) / 128, Dm / 64), 256>>>(Wo, bo, out);
}

// round 2
// speedup vs baseline: 3.5292x; 3.5292x over previous
#include <cuda_runtime.h>

#define Bb 2
#define Ls 2048
#define Dm 1024
#define Hh 16
#define Dk 64
#define Dv 64
#define BHN (Bb*Hh)

// Scratch (static device arrays — no runtime allocation)
__device__ float g_Q[(size_t)Bb*Hh*Ls*Dk];
__device__ float g_K[(size_t)Bb*Hh*Ls*Dk];
__device__ float g_V[(size_t)Bb*Hh*Ls*Dv];
__device__ float g_Z[(size_t)Bb*Ls*Hh*Dv];   // (B, L, H*Dv) head-concat

// ---- tf32 helpers ---------------------------------------------------------
__device__ __forceinline__ unsigned f2tf(float x){
    unsigned r; asm("cvt.rna.tf32.f32 %0, %1;" : "=r"(r) : "f"(x)); return r;
}
__device__ __forceinline__ float f2tff(float x){ return __uint_as_float(f2tf(x)); }

__device__ __forceinline__ void mma8(float c[4], const unsigned a[4], const unsigned b[2]){
    asm volatile("mma.sync.aligned.m16n8k8.row.col.f32.tf32.tf32.f32 "
        "{%0,%1,%2,%3},{%4,%5,%6,%7},{%8,%9},{%0,%1,%2,%3};"
        : "+f"(c[0]),"+f"(c[1]),"+f"(c[2]),"+f"(c[3])
        : "r"(a[0]),"r"(a[1]),"r"(a[2]),"r"(a[3]),"r"(b[0]),"r"(b[1]));
}

// ---------------------------------------------------------------------------
// Kernel 1: QKV projections. Out[l][n] = sum_d X[l][d] * W[h][d][n] + b[h][n]
// CTA tile 128m x 64n, BK=32. 8 warps, each 32m x 32n via m16n8k8 tf32 mma.
// smem: sa[m][k] row-major pitch 36, sb[k][n] row-major pitch 72.
// ---------------------------------------------------------------------------
#define SAP 36
#define SBP 72

__global__ __launch_bounds__(256) void qkv_kernel(
    const float* __restrict__ X,
    const float* __restrict__ Wq, const float* __restrict__ bq,
    const float* __restrict__ Wk, const float* __restrict__ bk,
    const float* __restrict__ Wv, const float* __restrict__ bv)
{
    __shared__ float sa[128][SAP];
    __shared__ float sb[32][SBP];

    int z   = blockIdx.y;              // 0..95
    int sel = z / BHN;
    int bh  = z - sel * BHN;
    int b   = bh / Hh;
    int h   = bh - b * Hh;

    const float* W; const float* bias; float* out;
    if (sel == 0)      { W = Wq; bias = bq; out = g_Q; }
    else if (sel == 1) { W = Wk; bias = bk; out = g_K; }
    else               { W = Wv; bias = bv; out = g_V; }
    W    += (size_t)h * Dm * Dk;
    bias += h * Dk;
    out  += (size_t)bh * Ls * Dk + (size_t)blockIdx.x * 128 * Dk;
    const float* A = X + (size_t)b * Ls * Dm + (size_t)blockIdx.x * 128 * Dm;

    int tid = threadIdx.x, lane = tid & 31, warp = tid >> 5;
    int qr = lane >> 2, qc = lane & 3;
    int m0 = (warp & 3) * 32, n0 = (warp >> 2) * 32;

    float c[2][4][4] = {};

    for (int kt = 0; kt < 32; ++kt) {
        // A tile: 128 x 32
#pragma unroll
        for (int i = 0; i < 4; i++) {
            int id = tid + 256 * i; int r = id >> 3, c4 = id & 7;
            float4 v = *(const float4*)(A + (size_t)r * Dm + kt * 32 + c4 * 4);
            float4 w; w.x = f2tff(v.x); w.y = f2tff(v.y); w.z = f2tff(v.z); w.w = f2tff(v.w);
            *(float4*)&sa[r][c4 * 4] = w;
        }
        // B tile: 32 x 64 (W is [d][n] row-major already)
#pragma unroll
        for (int i = 0; i < 2; i++) {
            int id = tid + 256 * i; int r = id >> 4, c4 = id & 15;
            float4 v = *(const float4*)(W + (size_t)(kt * 32 + r) * Dk + c4 * 4);
            float4 w; w.x = f2tff(v.x); w.y = f2tff(v.y); w.z = f2tff(v.z); w.w = f2tff(v.w);
            *(float4*)&sb[r][c4 * 4] = w;
        }
        __syncthreads();

#pragma unroll
        for (int ks = 0; ks < 4; ++ks) {
            unsigned a[2][4];
#pragma unroll
            for (int mi = 0; mi < 2; mi++) {
                a[mi][0] = __float_as_uint(sa[m0 + mi * 16 + qr    ][ks * 8 + qc    ]);
                a[mi][1] = __float_as_uint(sa[m0 + mi * 16 + qr + 8][ks * 8 + qc    ]);
                a[mi][2] = __float_as_uint(sa[m0 + mi * 16 + qr    ][ks * 8 + qc + 4]);
                a[mi][3] = __float_as_uint(sa[m0 + mi * 16 + qr + 8][ks * 8 + qc + 4]);
            }
#pragma unroll
            for (int nf = 0; nf < 4; nf++) {
                unsigned bb[2];
                bb[0] = __float_as_uint(sb[ks * 8 + qc    ][n0 + nf * 8 + qr]);
                bb[1] = __float_as_uint(sb[ks * 8 + qc + 4][n0 + nf * 8 + qr]);
                mma8(c[0][nf], a[0], bb);
                mma8(c[1][nf], a[1], bb);
            }
        }
        __syncthreads();
    }

#pragma unroll
    for (int mi = 0; mi < 2; mi++) {
#pragma unroll
        for (int nf = 0; nf < 4; nf++) {
            int col = n0 + nf * 8 + 2 * qc;
            float bx = bias[col], by = bias[col + 1];
            int row = m0 + mi * 16 + qr;
            float2 v0 = make_float2(c[mi][nf][0] + bx, c[mi][nf][1] + by);
            float2 v1 = make_float2(c[mi][nf][2] + bx, c[mi][nf][3] + by);
            *(float2*)(out + (size_t)row * Dk + col) = v0;
            *(float2*)(out + (size_t)(row + 8) * Dk + col) = v1;
        }
    }
}

// ---------------------------------------------------------------------------
// Kernel 2: flash attention per (b,h). CTA = 128 q-rows, KV tiles of 128.
// 8 warps, each owns 16 q-rows x full 128 keys: S and P live in registers,
// online softmax in registers (quad shfl), P->A-fragment via intra-quad shfl.
// ---------------------------------------------------------------------------
#define QSP 68
#define VSP 72

__global__ __launch_bounds__(256) void flash_kernel()
{
    extern __shared__ float sm[];
    float* qs  = sm;                   // [128][68]
    float* ksm = qs + 128 * QSP;       // [128][68]
    float* vsm = ksm + 128 * QSP;      // [128][72]

    int bh = blockIdx.y;
    int q0 = blockIdx.x * 128;
    const float* Qg = g_Q + (size_t)bh * Ls * Dk + (size_t)q0 * Dk;
    const float* Kg = g_K + (size_t)bh * Ls * Dk;
    const float* Vg = g_V + (size_t)bh * Ls * Dv;
    int b = bh >> 4, h = bh & 15;

    int tid = threadIdx.x, lane = tid & 31, warp = tid >> 5;
    int qr = lane >> 2, qc = lane & 3;
    int m0 = warp * 16;

    // load Q tile (scale folded, tf32-rounded)
#pragma unroll
    for (int i = 0; i < 8; i++) {
        int id = tid + 256 * i; int r = id >> 4, c4 = id & 15;
        float4 v = *(const float4*)(Qg + (size_t)r * Dk + c4 * 4);
        float4 w; w.x = f2tff(v.x * 0.125f); w.y = f2tff(v.y * 0.125f);
                  w.z = f2tff(v.z * 0.125f); w.w = f2tff(v.w * 0.125f);
        *(float4*)&qs[r * QSP + c4 * 4] = w;
    }

    float co[8][4] = {};
    float mA = -1e30f, mB = -1e30f, lA = 0.f, lB = 0.f;

    int base = lane & ~3;
    int s0 = base + (qc >> 1), s1 = s0 + 2;
    bool odd = (qc & 1);

    for (int t = 0; t < Ls / 128; ++t) {
        // load K, V tiles (row-major, tf32-rounded)
#pragma unroll
        for (int i = 0; i < 8; i++) {
            int id = tid + 256 * i; int r = id >> 4, c4 = id & 15;
            float4 v = *(const float4*)(Kg + (size_t)(t * 128 + r) * Dk + c4 * 4);
            float4 w; w.x = f2tff(v.x); w.y = f2tff(v.y); w.z = f2tff(v.z); w.w = f2tff(v.w);
            *(float4*)&ksm[r * QSP + c4 * 4] = w;
            float4 u = *(const float4*)(Vg + (size_t)(t * 128 + r) * Dv + c4 * 4);
            float4 x; x.x = f2tff(u.x); x.y = f2tff(u.y); x.z = f2tff(u.z); x.w = f2tff(u.w);
            *(float4*)&vsm[r * VSP + c4 * 4] = x;
        }
        __syncthreads();

        // S = Q K^T : per warp 16 x 128 in registers
        float sc[16][4] = {};
#pragma unroll
        for (int ks = 0; ks < 8; ++ks) {
            unsigned a[4];
            a[0] = __float_as_uint(qs[(m0 + qr    ) * QSP + ks * 8 + qc    ]);
            a[1] = __float_as_uint(qs[(m0 + qr + 8) * QSP + ks * 8 + qc    ]);
            a[2] = __float_as_uint(qs[(m0 + qr    ) * QSP + ks * 8 + qc + 4]);
            a[3] = __float_as_uint(qs[(m0 + qr + 8) * QSP + ks * 8 + qc + 4]);
#pragma unroll
            for (int nf = 0; nf < 16; nf++) {
                unsigned bb[2];
                bb[0] = __float_as_uint(ksm[(nf * 8 + qr) * QSP + ks * 8 + qc    ]);
                bb[1] = __float_as_uint(ksm[(nf * 8 + qr) * QSP + ks * 8 + qc + 4]);
                mma8(sc[nf], a, bb);
            }
        }

        // online softmax (rows qr and qr+8), all in registers
        float mxA = -1e30f, mxB = -1e30f;
#pragma unroll
        for (int nf = 0; nf < 16; nf++) {
            mxA = fmaxf(mxA, fmaxf(sc[nf][0], sc[nf][1]));
            mxB = fmaxf(mxB, fmaxf(sc[nf][2], sc[nf][3]));
        }
        mxA = fmaxf(mxA, __shfl_xor_sync(0xffffffffu, mxA, 1));
        mxA = fmaxf(mxA, __shfl_xor_sync(0xffffffffu, mxA, 2));
        mxB = fmaxf(mxB, __shfl_xor_sync(0xffffffffu, mxB, 1));
        mxB = fmaxf(mxB, __shfl_xor_sync(0xffffffffu, mxB, 2));

        float mnA = fmaxf(mA, mxA), mnB = fmaxf(mB, mxB);
        float aAl = __expf(mA - mnA), aBl = __expf(mB - mnB);
        float sA = 0.f, sB = 0.f;
#pragma unroll
        for (int nf = 0; nf < 16; nf++) {
            float p0 = __expf(sc[nf][0] - mnA);
            float p1 = __expf(sc[nf][1] - mnA);
            float p2 = __expf(sc[nf][2] - mnB);
            float p3 = __expf(sc[nf][3] - mnB);
            sA += p0 + p1; sB += p2 + p3;
            sc[nf][0] = f2tff(p0); sc[nf][1] = f2tff(p1);
            sc[nf][2] = f2tff(p2); sc[nf][3] = f2tff(p3);
        }
        sA += __shfl_xor_sync(0xffffffffu, sA, 1);
        sA += __shfl_xor_sync(0xffffffffu, sA, 2);
        sB += __shfl_xor_sync(0xffffffffu, sB, 1);
        sB += __shfl_xor_sync(0xffffffffu, sB, 2);
        lA = lA * aAl + sA; mA = mnA;
        lB = lB * aBl + sB; mB = mnB;

#pragma unroll
        for (int vf = 0; vf < 8; vf++) {
            co[vf][0] *= aAl; co[vf][1] *= aAl;
            co[vf][2] *= aBl; co[vf][3] *= aBl;
        }

        // O += P V : P (C-layout regs) -> A-fragments via intra-quad shfl
#pragma unroll
        for (int kk = 0; kk < 16; ++kk) {
            float t00 = __shfl_sync(0xffffffffu, sc[kk][0], s0);
            float t01 = __shfl_sync(0xffffffffu, sc[kk][1], s0);
            float t10 = __shfl_sync(0xffffffffu, sc[kk][2], s0);
            float t11 = __shfl_sync(0xffffffffu, sc[kk][3], s0);
            float u00 = __shfl_sync(0xffffffffu, sc[kk][0], s1);
            float u01 = __shfl_sync(0xffffffffu, sc[kk][1], s1);
            float u10 = __shfl_sync(0xffffffffu, sc[kk][2], s1);
            float u11 = __shfl_sync(0xffffffffu, sc[kk][3], s1);
            unsigned a[4];
            a[0] = __float_as_uint(odd ? t01 : t00);
            a[1] = __float_as_uint(odd ? t11 : t10);
            a[2] = __float_as_uint(odd ? u01 : u00);
            a[3] = __float_as_uint(odd ? u11 : u10);
#pragma unroll
            for (int vf = 0; vf < 8; vf++) {
                unsigned bb[2];
                bb[0] = __float_as_uint(vsm[(kk * 8 + qc    ) * VSP + vf * 8 + qr]);
                bb[1] = __float_as_uint(vsm[(kk * 8 + qc + 4) * VSP + vf * 8 + qr]);
                mma8(co[vf], a, bb);
            }
        }
        __syncthreads();
    }

    float iA = 1.0f / lA, iB = 1.0f / lB;
    float* Zg = g_Z + ((size_t)(b * Ls + q0 + m0)) * (Hh * Dv) + h * Dv;
#pragma unroll
    for (int vf = 0; vf < 8; vf++) {
        int col = vf * 8 + 2 * qc;
        float2 v0 = make_float2(co[vf][0] * iA, co[vf][1] * iA);
        float2 v1 = make_float2(co[vf][2] * iB, co[vf][3] * iB);
        *(float2*)(Zg + (size_t)qr * (Hh * Dv) + col) = v0;
        *(float2*)(Zg + (size_t)(qr + 8) * (Hh * Dv) + col) = v1;
    }
}

// ---------------------------------------------------------------------------
// Kernel 3: output projection. out[m][n] = sum_k Z[m][k]*Wo[n][k] + bo[n]
// M=4096, N=1024, K=1024. CTA tile 128m x 64n, BK=32, same warp mma tiling.
// B fragments read directly from row-major Wo tile (col-major k x n view).
// ---------------------------------------------------------------------------
__global__ __launch_bounds__(256) void oproj_kernel(
    const float* __restrict__ Wo, const float* __restrict__ bo,
    float* __restrict__ out)
{
    __shared__ float sa[128][SAP];
    __shared__ float swo[64][SAP];
    const int N = Dm, K = Hh * Dv;

    const float* A = g_Z + (size_t)blockIdx.x * 128 * K;
    int n0g = blockIdx.y * 64;

    int tid = threadIdx.x, lane = tid & 31, warp = tid >> 5;
    int qr = lane >> 2, qc = lane & 3;
    int m0 = (warp & 3) * 32, n0 = (warp >> 2) * 32;

    float c[2][4][4] = {};

    for (int kt = 0; kt < K / 32; ++kt) {
#pragma unroll
        for (int i = 0; i < 4; i++) {
            int id = tid + 256 * i; int r = id >> 3, c4 = id & 7;
            float4 v = *(const float4*)(A + (size_t)r * K + kt * 32 + c4 * 4);
            float4 w; w.x = f2tff(v.x); w.y = f2tff(v.y); w.z = f2tff(v.z); w.w = f2tff(v.w);
            *(float4*)&sa[r][c4 * 4] = w;
        }
#pragma unroll
        for (int i = 0; i < 2; i++) {
            int id = tid + 256 * i; int r = id >> 3, c4 = id & 7;
            float4 v = *(const float4*)(Wo + (size_t)(n0g + r) * K + kt * 32 + c4 * 4);
            float4 w; w.x = f2tff(v.x); w.y = f2tff(v.y); w.z = f2tff(v.z); w.w = f2tff(v.w);
            *(float4*)&swo[r][c4 * 4] = w;
        }
        __syncthreads();

#pragma unroll
        for (int ks = 0; ks < 4; ++ks) {
            unsigned a[2][4];
#pragma unroll
            for (int mi = 0; mi < 2; mi++) {
                a[mi][0] = __float_as_uint(sa[m0 + mi * 16 + qr    ][ks * 8 + qc    ]);
                a[mi][1] = __float_as_uint(sa[m0 + mi * 16 + qr + 8][ks * 8 + qc    ]);
                a[mi][2] = __float_as_uint(sa[m0 + mi * 16 + qr    ][ks * 8 + qc + 4]);
                a[mi][3] = __float_as_uint(sa[m0 + mi * 16 + qr + 8][ks * 8 + qc + 4]);
            }
#pragma unroll
            for (int nf = 0; nf < 4; nf++) {
                unsigned bb[2];
                bb[0] = __float_as_uint(swo[n0 + nf * 8 + qr][ks * 8 + qc    ]);
                bb[1] = __float_as_uint(swo[n0 + nf * 8 + qr][ks * 8 + qc + 4]);
                mma8(c[0][nf], a[0], bb);
                mma8(c[1][nf], a[1], bb);
            }
        }
        __syncthreads();
    }

#pragma unroll
    for (int mi = 0; mi < 2; mi++) {
#pragma unroll
        for (int nf = 0; nf < 4; nf++) {
            int col = n0g + n0 + nf * 8 + 2 * qc;
            float bx = bo[col], by = bo[col + 1];
            int row = blockIdx.x * 128 + m0 + mi * 16 + qr;
            float2 v0 = make_float2(c[mi][nf][0] + bx, c[mi][nf][1] + by);
            float2 v1 = make_float2(c[mi][nf][2] + bx, c[mi][nf][3] + by);
            *(float2*)(out + (size_t)row * N + col) = v0;
            *(float2*)(out + (size_t)(row + 8) * N + col) = v1;
        }
    }
}

// ---------------------------------------------------------------------------
extern "C" void kernel_launch(void* const* d_in, const int* in_sizes, int n_in,
                              void* d_out, int out_size)
{
    const float* X  = (const float*)d_in[0];
    const float* Wq = (const float*)d_in[1];
    const float* bq = (const float*)d_in[2];
    const float* Wk = (const float*)d_in[3];
    const float* bk = (const float*)d_in[4];
    const float* Wv = (const float*)d_in[5];
    const float* bv = (const float*)d_in[6];
    const float* Wo = (const float*)d_in[7];
    const float* bo = (const float*)d_in[8];
    float* out = (float*)d_out;

    (void)in_sizes; (void)n_in; (void)out_size;

    const int flash_smem = (128 * QSP * 2 + 128 * VSP) * (int)sizeof(float);
    cudaFuncSetAttribute(flash_kernel, cudaFuncAttributeMaxDynamicSharedMemorySize, flash_smem);

    qkv_kernel<<<dim3(Ls / 128, 3 * BHN), 256>>>(X, Wq, bq, Wk, bk, Wv, bv);
    flash_kernel<<<dim3(Ls / 128, BHN), 256, flash_smem>>>();
    oproj_kernel<<<dim3((Bb * Ls) / 128, Dm / 64), 256>>>(Wo, bo, out);
}